// round 11
// baseline (speedup 1.0000x reference)
#include <cuda_runtime.h>
#include <cuda_fp16.h>
#include <cstdint>

#define NN 100000
#define EE 1600000
#define CC 128
#define SCAN_B 1024
#define NB_SCAN ((NN + SCAN_B - 1) / SCAN_B)   // 98

typedef unsigned long long ull;

// ---------------- scratch (static device globals) ---------------------------
__device__ __half g_H[(size_t)NN * CC];   // gemm output (value matrix), fp16
__device__ __half g_Bh[(size_t)NN * CC];  // layer-1 aggregate output, fp16
__device__ __half g_Xh[(size_t)NN * CC];  // fp16 copy of input x
__device__ __half g_W1h[CC * CC];
__device__ __half g_W2h[CC * CC];
__device__ float  g_as[NN];
__device__ float  g_ad[NN];
__device__ int    g_src[EE];
__device__ int    g_dst[EE];
__device__ int    g_csr[EE];
__device__ int    g_off[NN + 1];
__device__ int    g_cur[NN];
__device__ int    g_bsum[NB_SCAN];
__device__ int    g_is64;

__device__ __forceinline__ float lrelu(float x) { return x > 0.f ? x : 0.2f * x; }

__device__ __forceinline__ uint32_t smem_u32(const void* p) {
    uint32_t a;
    asm("{ .reg .u64 t; cvta.to.shared.u64 t, %1; cvt.u32.u64 %0, t; }" : "=r"(a) : "l"(p));
    return a;
}

__device__ __forceinline__ void cp16(uint32_t dst, const void* src, int sz) {
    asm volatile("cp.async.cg.shared.global [%0], [%1], 16, %2;"
                 :: "r"(dst), "l"(src), "r"(sz) : "memory");
}
#define CP_COMMIT() asm volatile("cp.async.commit_group;" ::: "memory")
#define CP_WAIT0()  asm volatile("cp.async.wait_group 0;" ::: "memory")

#define LDSM4(r0, r1, r2, r3, addr) \
    asm volatile("ldmatrix.sync.aligned.m8n8.x4.shared.b16 {%0,%1,%2,%3}, [%4];" \
                 : "=r"(r0), "=r"(r1), "=r"(r2), "=r"(r3) : "r"(addr))

#define MMA16816(c, a, b0v, b1v) \
    asm volatile("mma.sync.aligned.m16n8k16.row.col.f32.f16.f16.f32 " \
                 "{%0,%1,%2,%3}, {%4,%5,%6,%7}, {%8,%9}, {%0,%1,%2,%3};" \
                 : "+f"((c)[0]), "+f"((c)[1]), "+f"((c)[2]), "+f"((c)[3]) \
                 : "r"((a)[0]), "r"((a)[1]), "r"((a)[2]), "r"((a)[3]), \
                   "r"(b0v), "r"(b1v))

// ---------------- edge-index dtype detection --------------------------------
__global__ void k_detect(const void* ei) {
    __shared__ int bad;
    if (threadIdx.x == 0) bad = 0;
    __syncthreads();
    const unsigned long long* p = (const unsigned long long*)ei;
    int b = 0;
    for (int i = threadIdx.x; i < 1024; i += blockDim.x)
        if ((p[i] >> 32) != 0ull) b = 1;
    if (b) bad = 1;
    __syncthreads();
    if (threadIdx.x == 0) g_is64 = bad ? 0 : 1;
}

// fp32 -> fp16 pre-conversion (x, W1, W2) + zero degree counters
__global__ void k_tohalf(const float* __restrict__ x,
                         const float* __restrict__ W1, const float* __restrict__ W2) {
    int i = blockIdx.x * blockDim.x + threadIdx.x;
    if (i < NN) g_cur[i] = 0;
    const float4* x4 = (const float4*)x;
    uint2* xo = (uint2*)g_Xh;
    if (i < NN * CC / 4) {
        float4 v = x4[i];
        __half2 a = __floats2half2_rn(v.x, v.y);
        __half2 b = __floats2half2_rn(v.z, v.w);
        xo[i] = make_uint2(*reinterpret_cast<uint32_t*>(&a), *reinterpret_cast<uint32_t*>(&b));
    }
    if (i < CC * CC / 4) {
        float4 v = ((const float4*)W1)[i];
        __half2 a = __floats2half2_rn(v.x, v.y);
        __half2 b = __floats2half2_rn(v.z, v.w);
        ((uint2*)g_W1h)[i] = make_uint2(*reinterpret_cast<uint32_t*>(&a), *reinterpret_cast<uint32_t*>(&b));
        float4 w = ((const float4*)W2)[i];
        __half2 c = __floats2half2_rn(w.x, w.y);
        __half2 d = __floats2half2_rn(w.z, w.w);
        ((uint2*)g_W2h)[i] = make_uint2(*reinterpret_cast<uint32_t*>(&c), *reinterpret_cast<uint32_t*>(&d));
    }
}

__global__ void k_convert(const void* ei) {
    int j = blockIdx.x * blockDim.x + threadIdx.x;
    if (j >= EE) return;
    int s, d;
    if (g_is64) {
        const long long* p = (const long long*)ei;
        s = (int)p[j];
        d = (int)p[EE + j];
    } else {
        const int* p = (const int*)ei;
        s = p[j];
        d = p[EE + j];
    }
    g_src[j] = s;
    g_dst[j] = d;
    atomicAdd(&g_cur[d], 1);
}

// ---------------- 2-level exclusive scan -> CSR offsets ---------------------
__global__ void k_scan1() {
    __shared__ int sh[SCAN_B];
    int tid = threadIdx.x;
    int i = blockIdx.x * SCAN_B + tid;
    int v = (i < NN) ? g_cur[i] : 0;
    sh[tid] = v;
    __syncthreads();
    for (int off = 1; off < SCAN_B; off <<= 1) {
        int t = (tid >= off) ? sh[tid - off] : 0;
        __syncthreads();
        sh[tid] += t;
        __syncthreads();
    }
    if (i < NN) g_off[i] = sh[tid] - v;
    if (tid == SCAN_B - 1) g_bsum[blockIdx.x] = sh[tid];
}

__global__ void k_scan2() {
    __shared__ int sh[128];
    int tid = threadIdx.x;
    int v = (tid < NB_SCAN) ? g_bsum[tid] : 0;
    sh[tid] = v;
    __syncthreads();
    for (int off = 1; off < 128; off <<= 1) {
        int t = (tid >= off) ? sh[tid - off] : 0;
        __syncthreads();
        sh[tid] += t;
        __syncthreads();
    }
    if (tid < NB_SCAN) g_bsum[tid] = sh[tid] - v;
}

__global__ void k_scan3() {
    int i = blockIdx.x * blockDim.x + threadIdx.x;
    if (i < NN) {
        int v = g_off[i] + g_bsum[i >> 10];
        g_off[i] = v;
        g_cur[i] = v;
    }
    if (i == 0) g_off[NN] = EE;
}

__global__ void k_scatter() {
    int j = blockIdx.x * blockDim.x + threadIdx.x;
    if (j >= EE) return;
    int d = g_dst[j];
    int p = atomicAdd(&g_cur[d], 1);
    g_csr[p] = g_src[j];
}

// ---------------- HMMA GEMM: H = Xh @ Wh^T + attention logits ---------------
// fp16 inputs loaded via cp.async into XOR-swizzled smem. 8 warps, 128x128x128.
// avs/avd staged in smem (eliminates 16K scalar LDG per CTA in the epilogue).
#define ROWB 256                 // bytes per smem row (128 halves)
#define DPITCH 136               // halves per row of D staging (272B, 16B-aligned)
#define SMEM_GEMM (65536 + 1024) // A/B tiles (reused as D) + avs/avd stage

__global__ void __launch_bounds__(256, 2)
k_gemm_mma(const __half* __restrict__ Xh, const __half* __restrict__ Wh,
           const float* __restrict__ avs, const float* __restrict__ avd,
           __half* __restrict__ H) {
    extern __shared__ char sm[];
    char* smA = sm;
    char* smB = sm + 32768;
    float* sAV = (float*)(sm + 65536);   // [0:128) avs, [128:256) avd
    int tid = threadIdx.x;
    int lane = tid & 31, wid = tid >> 5;
    int row0 = blockIdx.x * 128;

    uint32_t aBase = smem_u32(smA), bBase = smem_u32(smB);

    // ---- async load: X tile (zfill tail) + W, both fp16, swizzled ---------
#pragma unroll
    for (int i = tid; i < 2048; i += 256) {
        int r = i >> 4, c8 = i & 15;
        int gr = row0 + r;
        int sz = (gr < NN) ? 16 : 0;
        const __half* src = Xh + (size_t)(gr < NN ? gr : 0) * CC + c8 * 8;
        cp16(aBase + r * ROWB + (((c8 ^ (r & 7)) & 15) << 4), src, sz);
        cp16(bBase + r * ROWB + (((c8 ^ (r & 7)) & 15) << 4), Wh + r * CC + c8 * 8, 16);
    }
    CP_COMMIT();
    // stage attention vectors while TMA... while cp.async is in flight
    if (tid < 128) {
        sAV[tid] = avs[tid];
        sAV[128 + tid] = avd[tid];
    }
    CP_WAIT0();
    __syncthreads();

    // ---- mainloop ----------------------------------------------------------
    int warpM = wid & 3, warpN = wid >> 2;
    float acc[2][8][4];
#pragma unroll
    for (int mt = 0; mt < 2; mt++)
#pragma unroll
        for (int nt = 0; nt < 8; nt++)
#pragma unroll
            for (int j = 0; j < 4; j++) acc[mt][nt][j] = 0.f;

#pragma unroll
    for (int ks = 0; ks < 8; ks++) {
        uint32_t kh = (uint32_t)(ks * 2 + (lane >> 4));
        uint32_t ar[2][4];
#pragma unroll
        for (int mt = 0; mt < 2; mt++) {
            int r = warpM * 32 + mt * 16 + (lane & 15);
            uint32_t addr = aBase + r * ROWB + (((kh ^ (uint32_t)(r & 7)) & 15u) << 4);
            LDSM4(ar[mt][0], ar[mt][1], ar[mt][2], ar[mt][3], addr);
        }
        uint32_t br[4][4];
#pragma unroll
        for (int nt = 0; nt < 4; nt++) {
            int n = warpN * 64 + nt * 16 + (lane & 15);
            uint32_t addr = bBase + n * ROWB + (((kh ^ (uint32_t)(n & 7)) & 15u) << 4);
            LDSM4(br[nt][0], br[nt][1], br[nt][2], br[nt][3], addr);
        }
#pragma unroll
        for (int mt = 0; mt < 2; mt++)
#pragma unroll
            for (int nt = 0; nt < 4; nt++) {
                MMA16816(acc[mt][nt * 2 + 0], ar[mt], br[nt][0], br[nt][2]);
                MMA16816(acc[mt][nt * 2 + 1], ar[mt], br[nt][1], br[nt][3]);
            }
    }

    // ---- stage D into smem (reuse A/B regions), pitch 136 halves -----------
    __syncthreads();
    __half* D = (__half*)sm;
    int q = lane & 3, g = lane >> 2;
#pragma unroll
    for (int mt = 0; mt < 2; mt++) {
        int r0 = warpM * 32 + mt * 16 + g;
        int r1 = r0 + 8;
#pragma unroll
        for (int n8 = 0; n8 < 8; n8++) {
            int col = warpN * 64 + n8 * 8 + 2 * q;
            __half2 lo = __floats2half2_rn(acc[mt][n8][0], acc[mt][n8][1]);
            __half2 hi = __floats2half2_rn(acc[mt][n8][2], acc[mt][n8][3]);
            *(__half2*)(D + r0 * DPITCH + col) = lo;
            *(__half2*)(D + r1 * DPITCH + col) = hi;
        }
    }
    __syncthreads();

    // ---- coalesced H store + logits (2 threads per row) --------------------
    {
        int r = tid >> 1, hhalf = tid & 1;
        int gr = row0 + r;
        const __half* drow = D + r * DPITCH + hhalf * 64;
        const float4* av4 = (const float4*)(sAV + hhalf * 64);
        const float4* ad4 = (const float4*)(sAV + 128 + hhalf * 64);
        float ps = 0.f, pd = 0.f;
        uint4 chunks[8];
#pragma unroll
        for (int i = 0; i < 8; i++) chunks[i] = *(const uint4*)(drow + i * 8);
#pragma unroll
        for (int i = 0; i < 8; i++) {
            const uint32_t* cw = (const uint32_t*)&chunks[i];
            float4 va = av4[i * 2], vb = av4[i * 2 + 1];
            float4 wa = ad4[i * 2], wb = ad4[i * 2 + 1];
            float2 f0 = __half22float2(*reinterpret_cast<const __half2*>(&cw[0]));
            float2 f1 = __half22float2(*reinterpret_cast<const __half2*>(&cw[1]));
            float2 f2 = __half22float2(*reinterpret_cast<const __half2*>(&cw[2]));
            float2 f3 = __half22float2(*reinterpret_cast<const __half2*>(&cw[3]));
            ps += f0.x * va.x + f0.y * va.y + f1.x * va.z + f1.y * va.w
                + f2.x * vb.x + f2.y * vb.y + f3.x * vb.z + f3.y * vb.w;
            pd += f0.x * wa.x + f0.y * wa.y + f1.x * wa.z + f1.y * wa.w
                + f2.x * wb.x + f2.y * wb.y + f3.x * wb.z + f3.y * wb.w;
        }
        float pso = ps + __shfl_xor_sync(0xffffffffu, ps, 1);
        float pdo = pd + __shfl_xor_sync(0xffffffffu, pd, 1);
        if (gr < NN) {
            uint4* dst = (uint4*)(H + (size_t)gr * CC + hhalf * 64);
#pragma unroll
            for (int i = 0; i < 8; i++) dst[i] = chunks[i];
            if (hhalf == 0) {
                g_as[gr] = pso;
                g_ad[gr] = pdo;
            }
        }
    }
}

// ---------------- aggregate core: online softmax, warp per dst --------------
// dual accumulator sets for 2x load MLP in the gather loop
__device__ __forceinline__ float4 agg_node(const __half* __restrict__ Hh,
                                           const float* __restrict__ bias,
                                           int d, int lane, int wslot,
                                           float sw_buf[8][32], int ss_buf[8][32]) {
    int beg = g_off[d], end = g_off[d + 1];
    float add = g_ad[d];
    float m = lrelu(g_as[d] + add);     // self-loop logit

    uint2 hu = ((const uint2*)(Hh + (size_t)d * CC))[lane];
    float2 lo = __half22float2(*reinterpret_cast<__half2*>(&hu.x));
    float2 hi = __half22float2(*reinterpret_cast<__half2*>(&hu.y));
    float ax = lo.x, ay = lo.y, az = hi.x, aw = hi.y;
    float bx = 0.f, by = 0.f, bz = 0.f, bw = 0.f;
    float dsum = (lane == 0) ? 1.f : 0.f;

    for (int pb = beg; pb < end; pb += 32) {
        int p = pb + lane;
        float e = -1e30f;
        int s = 0;
        if (p < end) {
            s = g_csr[p];
            e = lrelu(g_as[s] + add);
        }
        float cm = e;
#pragma unroll
        for (int o = 16; o; o >>= 1) cm = fmaxf(cm, __shfl_xor_sync(0xffffffffu, cm, o));
        if (cm > m) {
            float sc = __expf(m - cm);
            ax *= sc; ay *= sc; az *= sc; aw *= sc;
            bx *= sc; by *= sc; bz *= sc; bw *= sc;
            dsum *= sc;
            m = cm;
        }
        float wj = (p < end) ? __expf(e - m) : 0.f;
        dsum += wj;
        sw_buf[wslot][lane] = wj;
        ss_buf[wslot][lane] = s;
        __syncwarp();
        int cnt = min(32, end - pb);
        int k = 0;
#pragma unroll 4
        for (; k + 1 < cnt; k += 2) {
            float wk0 = sw_buf[wslot][k];
            float wk1 = sw_buf[wslot][k + 1];
            int sk0 = ss_buf[wslot][k];
            int sk1 = ss_buf[wslot][k + 1];
            uint2 g0 = ((const uint2*)(Hh + (size_t)sk0 * CC))[lane];
            uint2 g1 = ((const uint2*)(Hh + (size_t)sk1 * CC))[lane];
            float2 l0 = __half22float2(*reinterpret_cast<__half2*>(&g0.x));
            float2 h0 = __half22float2(*reinterpret_cast<__half2*>(&g0.y));
            float2 l1 = __half22float2(*reinterpret_cast<__half2*>(&g1.x));
            float2 h1 = __half22float2(*reinterpret_cast<__half2*>(&g1.y));
            ax += l0.x * wk0; ay += l0.y * wk0; az += h0.x * wk0; aw += h0.y * wk0;
            bx += l1.x * wk1; by += l1.y * wk1; bz += h1.x * wk1; bw += h1.y * wk1;
        }
        if (k < cnt) {
            float wk = sw_buf[wslot][k];
            int sk = ss_buf[wslot][k];
            uint2 gu = ((const uint2*)(Hh + (size_t)sk * CC))[lane];
            float2 glo = __half22float2(*reinterpret_cast<__half2*>(&gu.x));
            float2 ghi = __half22float2(*reinterpret_cast<__half2*>(&gu.y));
            ax += glo.x * wk; ay += glo.y * wk; az += ghi.x * wk; aw += ghi.y * wk;
        }
        __syncwarp();
    }
    ax += bx; ay += by; az += bz; aw += bw;
#pragma unroll
    for (int o = 16; o; o >>= 1) dsum += __shfl_xor_sync(0xffffffffu, dsum, o);
    float inv = 1.0f / dsum;

    float4 bv = ((const float4*)bias)[lane];
    float4 r;
    r.x = fmaxf(ax * inv + bv.x, 0.f);
    r.y = fmaxf(ay * inv + bv.y, 0.f);
    r.z = fmaxf(az * inv + bv.z, 0.f);
    r.w = fmaxf(aw * inv + bv.w, 0.f);
    return r;
}

// layer 1: write fp16 output (identical values to what GEMM-2 would convert)
__global__ void k_agg1(const __half* __restrict__ Hh, __half* __restrict__ OUT,
                       const float* __restrict__ bias) {
    __shared__ float s_w[8][32];
    __shared__ int   s_s[8][32];
    int gw = (blockIdx.x * blockDim.x + threadIdx.x) >> 5;
    if (gw >= NN) return;
    int lane = threadIdx.x & 31, ws = threadIdx.x >> 5;
    float4 r = agg_node(Hh, bias, gw, lane, ws, s_w, s_s);
    __half2 o0 = __floats2half2_rn(r.x, r.y);
    __half2 o1 = __floats2half2_rn(r.z, r.w);
    ((uint2*)(OUT + (size_t)gw * CC))[lane] =
        make_uint2(*reinterpret_cast<uint32_t*>(&o0), *reinterpret_cast<uint32_t*>(&o1));
}

__global__ void k_agg2_heads(const __half* __restrict__ Hh,
                             const float* __restrict__ bias,
                             const float* __restrict__ Wf, const float* __restrict__ bf,
                             const float* __restrict__ Ws, const float* __restrict__ bs,
                             float* __restrict__ out) {
    __shared__ float s_w[8][32];
    __shared__ int   s_s[8][32];
    int gw = (blockIdx.x * blockDim.x + threadIdx.x) >> 5;
    if (gw >= NN) return;
    int lane = threadIdx.x & 31, ws = threadIdx.x >> 5;
    float4 r = agg_node(Hh, bias, gw, lane, ws, s_w, s_s);

#pragma unroll
    for (int q = 0; q < 3; q++) {
        float4 w = ((const float4*)(Wf + q * CC))[lane];
        float p = r.x * w.x + r.y * w.y + r.z * w.z + r.w * w.w;
#pragma unroll
        for (int o = 16; o; o >>= 1) p += __shfl_xor_sync(0xffffffffu, p, o);
        if (lane == 0) out[(size_t)gw * 3 + q] = p + bf[q];
    }
#pragma unroll
    for (int q = 0; q < 7; q++) {
        float4 w = ((const float4*)(Ws + q * CC))[lane];
        float p = r.x * w.x + r.y * w.y + r.z * w.z + r.w * w.w;
#pragma unroll
        for (int o = 16; o; o >>= 1) p += __shfl_xor_sync(0xffffffffu, p, o);
        if (lane == 0) out[(size_t)NN * 3 + (size_t)gw * 7 + q] = p + bs[q];
    }
}

// ---------------- launch ----------------------------------------------------
extern "C" void kernel_launch(void* const* d_in, const int* in_sizes, int n_in,
                              void* d_out, int out_size) {
    const float* x      = (const float*)d_in[0];
    const void*  ei     = d_in[1];
    const float* W1     = (const float*)d_in[2];
    const float* a_src1 = (const float*)d_in[3];
    const float* a_dst1 = (const float*)d_in[4];
    const float* b1     = (const float*)d_in[5];
    const float* W2     = (const float*)d_in[6];
    const float* a_src2 = (const float*)d_in[7];
    const float* a_dst2 = (const float*)d_in[8];
    const float* b2     = (const float*)d_in[9];
    const float* Wf     = (const float*)d_in[10];
    const float* bf     = (const float*)d_in[11];
    const float* Ws     = (const float*)d_in[12];
    const float* bs     = (const float*)d_in[13];
    float* out = (float*)d_out;

    cudaFuncSetAttribute(k_gemm_mma, cudaFuncAttributeMaxDynamicSharedMemorySize, SMEM_GEMM);

    __half *gH, *gBh, *gXh, *gW1h, *gW2h;
    cudaGetSymbolAddress((void**)&gH,   g_H);
    cudaGetSymbolAddress((void**)&gBh,  g_Bh);
    cudaGetSymbolAddress((void**)&gXh,  g_Xh);
    cudaGetSymbolAddress((void**)&gW1h, g_W1h);
    cudaGetSymbolAddress((void**)&gW2h, g_W2h);

    int gemm_grid = (NN + 127) / 128;    // 782
    int agg_grid  = (NN + 7) / 8;        // 12500
    int conv_grid = (NN * CC / 4 + 255) / 256;  // 12500

    // launch order keeps gemm1 at index 3 (= ncu capture slot 5)
    k_detect<<<1, 256>>>(ei);
    k_tohalf<<<conv_grid, 256>>>(x, W1, W2);   // also zeroes g_cur
    k_convert<<<EE / 256, 256>>>(ei);
    k_gemm_mma<<<gemm_grid, 256, SMEM_GEMM>>>(gXh, gW1h, a_src1, a_dst1, gH);
    k_scan1<<<NB_SCAN, SCAN_B>>>();
    k_scan2<<<1, 128>>>();
    k_scan3<<<(NN + 255) / 256, 256>>>();
    k_scatter<<<EE / 256, 256>>>();

    // layer 1 aggregate (fp16 out)
    k_agg1<<<agg_grid, 256>>>(gH, gBh, b1);

    // layer 2 GEMM + fused aggregate/heads
    k_gemm_mma<<<gemm_grid, 256, SMEM_GEMM>>>(gBh, gW2h, a_src2, a_dst2, gH);
    k_agg2_heads<<<agg_grid, 256>>>(gH, b2, Wf, bf, Ws, bs, out);

    (void)in_sizes; (void)n_in; (void)out_size;
}

// round 12
// speedup vs baseline: 1.0999x; 1.0999x over previous
#include <cuda_runtime.h>
#include <cuda_fp16.h>
#include <cstdint>

#define NN 100000
#define EE 1600000
#define CC 128
#define SCAN_B 1024
#define NB_SCAN ((NN + SCAN_B - 1) / SCAN_B)   // 98

typedef unsigned long long ull;

// ---------------- scratch (static device globals) ---------------------------
__device__ __half g_H[(size_t)NN * CC];   // gemm output (value matrix), fp16
__device__ __half g_Bh[(size_t)NN * CC];  // layer-1 aggregate output, fp16
__device__ __half g_Xh[(size_t)NN * CC];  // fp16 copy of input x
__device__ __half g_W1h[CC * CC];
__device__ __half g_W2h[CC * CC];
__device__ float  g_as[NN];
__device__ float  g_ad[NN];
__device__ int    g_src[EE];
__device__ int    g_dst[EE];
__device__ int    g_csr[EE];
__device__ int    g_off[NN + 1];
__device__ int    g_cur[NN];
__device__ int    g_bsum[NB_SCAN];
__device__ int    g_is64;

__device__ __forceinline__ float lrelu(float x) { return x > 0.f ? x : 0.2f * x; }

__device__ __forceinline__ uint32_t smem_u32(const void* p) {
    uint32_t a;
    asm("{ .reg .u64 t; cvta.to.shared.u64 t, %1; cvt.u32.u64 %0, t; }" : "=r"(a) : "l"(p));
    return a;
}

__device__ __forceinline__ void cp16(uint32_t dst, const void* src, int sz) {
    asm volatile("cp.async.cg.shared.global [%0], [%1], 16, %2;"
                 :: "r"(dst), "l"(src), "r"(sz) : "memory");
}
#define CP_COMMIT() asm volatile("cp.async.commit_group;" ::: "memory")
#define CP_WAIT0()  asm volatile("cp.async.wait_group 0;" ::: "memory")

#define LDSM4(r0, r1, r2, r3, addr) \
    asm volatile("ldmatrix.sync.aligned.m8n8.x4.shared.b16 {%0,%1,%2,%3}, [%4];" \
                 : "=r"(r0), "=r"(r1), "=r"(r2), "=r"(r3) : "r"(addr))

#define MMA16816(c, a, b0v, b1v) \
    asm volatile("mma.sync.aligned.m16n8k16.row.col.f32.f16.f16.f32 " \
                 "{%0,%1,%2,%3}, {%4,%5,%6,%7}, {%8,%9}, {%0,%1,%2,%3};" \
                 : "+f"((c)[0]), "+f"((c)[1]), "+f"((c)[2]), "+f"((c)[3]) \
                 : "r"((a)[0]), "r"((a)[1]), "r"((a)[2]), "r"((a)[3]), \
                   "r"(b0v), "r"(b1v))

// ---------------- edge-index dtype detection --------------------------------
__global__ void k_detect(const void* ei) {
    __shared__ int bad;
    if (threadIdx.x == 0) bad = 0;
    __syncthreads();
    const unsigned long long* p = (const unsigned long long*)ei;
    int b = 0;
    for (int i = threadIdx.x; i < 1024; i += blockDim.x)
        if ((p[i] >> 32) != 0ull) b = 1;
    if (b) bad = 1;
    __syncthreads();
    if (threadIdx.x == 0) g_is64 = bad ? 0 : 1;
}

// fp32 -> fp16 pre-conversion (x, W1, W2) + zero degree counters
__global__ void k_tohalf(const float* __restrict__ x,
                         const float* __restrict__ W1, const float* __restrict__ W2) {
    int i = blockIdx.x * blockDim.x + threadIdx.x;
    if (i < NN) g_cur[i] = 0;
    const float4* x4 = (const float4*)x;
    uint2* xo = (uint2*)g_Xh;
    if (i < NN * CC / 4) {
        float4 v = x4[i];
        __half2 a = __floats2half2_rn(v.x, v.y);
        __half2 b = __floats2half2_rn(v.z, v.w);
        xo[i] = make_uint2(*reinterpret_cast<uint32_t*>(&a), *reinterpret_cast<uint32_t*>(&b));
    }
    if (i < CC * CC / 4) {
        float4 v = ((const float4*)W1)[i];
        __half2 a = __floats2half2_rn(v.x, v.y);
        __half2 b = __floats2half2_rn(v.z, v.w);
        ((uint2*)g_W1h)[i] = make_uint2(*reinterpret_cast<uint32_t*>(&a), *reinterpret_cast<uint32_t*>(&b));
        float4 w = ((const float4*)W2)[i];
        __half2 c = __floats2half2_rn(w.x, w.y);
        __half2 d = __floats2half2_rn(w.z, w.w);
        ((uint2*)g_W2h)[i] = make_uint2(*reinterpret_cast<uint32_t*>(&c), *reinterpret_cast<uint32_t*>(&d));
    }
}

__global__ void k_convert(const void* ei) {
    int j = blockIdx.x * blockDim.x + threadIdx.x;
    if (j >= EE) return;
    int s, d;
    if (g_is64) {
        const long long* p = (const long long*)ei;
        s = (int)p[j];
        d = (int)p[EE + j];
    } else {
        const int* p = (const int*)ei;
        s = p[j];
        d = p[EE + j];
    }
    g_src[j] = s;
    g_dst[j] = d;
    atomicAdd(&g_cur[d], 1);
}

// ---------------- 2-level exclusive scan -> CSR offsets ---------------------
__global__ void k_scan1() {
    __shared__ int sh[SCAN_B];
    int tid = threadIdx.x;
    int i = blockIdx.x * SCAN_B + tid;
    int v = (i < NN) ? g_cur[i] : 0;
    sh[tid] = v;
    __syncthreads();
    for (int off = 1; off < SCAN_B; off <<= 1) {
        int t = (tid >= off) ? sh[tid - off] : 0;
        __syncthreads();
        sh[tid] += t;
        __syncthreads();
    }
    if (i < NN) g_off[i] = sh[tid] - v;
    if (tid == SCAN_B - 1) g_bsum[blockIdx.x] = sh[tid];
}

__global__ void k_scan2() {
    __shared__ int sh[128];
    int tid = threadIdx.x;
    int v = (tid < NB_SCAN) ? g_bsum[tid] : 0;
    sh[tid] = v;
    __syncthreads();
    for (int off = 1; off < 128; off <<= 1) {
        int t = (tid >= off) ? sh[tid - off] : 0;
        __syncthreads();
        sh[tid] += t;
        __syncthreads();
    }
    if (tid < NB_SCAN) g_bsum[tid] = sh[tid] - v;
}

__global__ void k_scan3() {
    int i = blockIdx.x * blockDim.x + threadIdx.x;
    if (i < NN) {
        int v = g_off[i] + g_bsum[i >> 10];
        g_off[i] = v;
        g_cur[i] = v;
    }
    if (i == 0) g_off[NN] = EE;
}

__global__ void k_scatter() {
    int j = blockIdx.x * blockDim.x + threadIdx.x;
    if (j >= EE) return;
    int d = g_dst[j];
    int p = atomicAdd(&g_cur[d], 1);
    g_csr[p] = g_src[j];
}

// ---------------- HMMA GEMM: H = Xh @ Wh^T + attention logits ---------------
// M=64 tile, 128 threads (4 warps, each 32x64), 4 CTAs/SM for phase overlap.
#define ROWB 256                 // bytes per smem row (128 halves)
#define DPITCH 136               // halves per row of D staging (272B, 16B-aligned)
#define SMA 16384                // A tile: 64 rows x 256B
#define SMB 32768                // B tile: 128 rows x 256B
#define SMEM_GEMM (SMA + SMB + 1024)

__global__ void __launch_bounds__(128, 4)
k_gemm_mma(const __half* __restrict__ Xh, const __half* __restrict__ Wh,
           const float* __restrict__ avs, const float* __restrict__ avd,
           __half* __restrict__ H) {
    extern __shared__ char sm[];
    char* smA = sm;
    char* smB = sm + SMA;
    float* sAV = (float*)(sm + SMA + SMB);   // [0:128) avs, [128:256) avd
    int tid = threadIdx.x;
    int lane = tid & 31, wid = tid >> 5;
    int row0 = blockIdx.x * 64;

    uint32_t aBase = smem_u32(smA), bBase = smem_u32(smB);

    // ---- async load: X tile (64 rows, zfill tail) + W (128 rows) -----------
#pragma unroll
    for (int i = tid; i < 1024; i += 128) {
        int r = i >> 4, c8 = i & 15;
        int gr = row0 + r;
        int sz = (gr < NN) ? 16 : 0;
        const __half* src = Xh + (size_t)(gr < NN ? gr : 0) * CC + c8 * 8;
        cp16(aBase + r * ROWB + (((c8 ^ (r & 7)) & 15) << 4), src, sz);
    }
#pragma unroll
    for (int i = tid; i < 2048; i += 128) {
        int r = i >> 4, c8 = i & 15;
        cp16(bBase + r * ROWB + (((c8 ^ (r & 7)) & 15) << 4), Wh + r * CC + c8 * 8, 16);
    }
    CP_COMMIT();
    // stage attention vectors while cp.async is in flight
    sAV[tid] = avs[tid & 127];
    if (tid < 128) sAV[128 + tid] = avd[tid];
    CP_WAIT0();
    __syncthreads();

    // ---- mainloop: warpM = wid&1 (32 rows), warpN = wid>>1 (64 cols) -------
    int warpM = wid & 1, warpN = wid >> 1;
    float acc[2][8][4];
#pragma unroll
    for (int mt = 0; mt < 2; mt++)
#pragma unroll
        for (int nt = 0; nt < 8; nt++)
#pragma unroll
            for (int j = 0; j < 4; j++) acc[mt][nt][j] = 0.f;

#pragma unroll
    for (int ks = 0; ks < 8; ks++) {
        uint32_t kh = (uint32_t)(ks * 2 + (lane >> 4));
        uint32_t ar[2][4];
#pragma unroll
        for (int mt = 0; mt < 2; mt++) {
            int r = warpM * 32 + mt * 16 + (lane & 15);
            uint32_t addr = aBase + r * ROWB + (((kh ^ (uint32_t)(r & 7)) & 15u) << 4);
            LDSM4(ar[mt][0], ar[mt][1], ar[mt][2], ar[mt][3], addr);
        }
        uint32_t br[4][4];
#pragma unroll
        for (int nt = 0; nt < 4; nt++) {
            int n = warpN * 64 + nt * 16 + (lane & 15);
            uint32_t addr = bBase + n * ROWB + (((kh ^ (uint32_t)(n & 7)) & 15u) << 4);
            LDSM4(br[nt][0], br[nt][1], br[nt][2], br[nt][3], addr);
        }
#pragma unroll
        for (int mt = 0; mt < 2; mt++)
#pragma unroll
            for (int nt = 0; nt < 4; nt++) {
                MMA16816(acc[mt][nt * 2 + 0], ar[mt], br[nt][0], br[nt][2]);
                MMA16816(acc[mt][nt * 2 + 1], ar[mt], br[nt][1], br[nt][3]);
            }
    }

    // ---- stage D into smem (reuse A/B regions), pitch 136 halves -----------
    __syncthreads();
    __half* D = (__half*)sm;
    int q = lane & 3, g = lane >> 2;
#pragma unroll
    for (int mt = 0; mt < 2; mt++) {
        int r0 = warpM * 32 + mt * 16 + g;
        int r1 = r0 + 8;
#pragma unroll
        for (int n8 = 0; n8 < 8; n8++) {
            int col = warpN * 64 + n8 * 8 + 2 * q;
            __half2 lo = __floats2half2_rn(acc[mt][n8][0], acc[mt][n8][1]);
            __half2 hi = __floats2half2_rn(acc[mt][n8][2], acc[mt][n8][3]);
            *(__half2*)(D + r0 * DPITCH + col) = lo;
            *(__half2*)(D + r1 * DPITCH + col) = hi;
        }
    }
    __syncthreads();

    // ---- coalesced H store + logits (2 threads per row, 64 rows) -----------
    {
        int r = tid >> 1, hhalf = tid & 1;
        int gr = row0 + r;
        const __half* drow = D + r * DPITCH + hhalf * 64;
        const float4* av4 = (const float4*)(sAV + hhalf * 64);
        const float4* ad4 = (const float4*)(sAV + 128 + hhalf * 64);
        float ps = 0.f, pd = 0.f;
        uint4 chunks[8];
#pragma unroll
        for (int i = 0; i < 8; i++) chunks[i] = *(const uint4*)(drow + i * 8);
#pragma unroll
        for (int i = 0; i < 8; i++) {
            const uint32_t* cw = (const uint32_t*)&chunks[i];
            float4 va = av4[i * 2], vb = av4[i * 2 + 1];
            float4 wa = ad4[i * 2], wb = ad4[i * 2 + 1];
            float2 f0 = __half22float2(*reinterpret_cast<const __half2*>(&cw[0]));
            float2 f1 = __half22float2(*reinterpret_cast<const __half2*>(&cw[1]));
            float2 f2 = __half22float2(*reinterpret_cast<const __half2*>(&cw[2]));
            float2 f3 = __half22float2(*reinterpret_cast<const __half2*>(&cw[3]));
            ps += f0.x * va.x + f0.y * va.y + f1.x * va.z + f1.y * va.w
                + f2.x * vb.x + f2.y * vb.y + f3.x * vb.z + f3.y * vb.w;
            pd += f0.x * wa.x + f0.y * wa.y + f1.x * wa.z + f1.y * wa.w
                + f2.x * wb.x + f2.y * wb.y + f3.x * wb.z + f3.y * wb.w;
        }
        float pso = ps + __shfl_xor_sync(0xffffffffu, ps, 1);
        float pdo = pd + __shfl_xor_sync(0xffffffffu, pd, 1);
        if (gr < NN) {
            uint4* dst = (uint4*)(H + (size_t)gr * CC + hhalf * 64);
#pragma unroll
            for (int i = 0; i < 8; i++) dst[i] = chunks[i];
            if (hhalf == 0) {
                g_as[gr] = pso;
                g_ad[gr] = pdo;
            }
        }
    }
}

// ---------------- aggregate core: online softmax, warp per dst --------------
// (R10 known-good version: single accumulator set, compiler unroll 8)
__device__ __forceinline__ float4 agg_node(const __half* __restrict__ Hh,
                                           const float* __restrict__ bias,
                                           int d, int lane, int wslot,
                                           float sw_buf[8][32], int ss_buf[8][32]) {
    int beg = g_off[d], end = g_off[d + 1];
    float add = g_ad[d];
    float m = lrelu(g_as[d] + add);     // self-loop logit

    uint2 hu = ((const uint2*)(Hh + (size_t)d * CC))[lane];
    float2 lo = __half22float2(*reinterpret_cast<__half2*>(&hu.x));
    float2 hi = __half22float2(*reinterpret_cast<__half2*>(&hu.y));
    float ax = lo.x, ay = lo.y, az = hi.x, aw = hi.y;
    float dsum = (lane == 0) ? 1.f : 0.f;

    for (int pb = beg; pb < end; pb += 32) {
        int p = pb + lane;
        float e = -1e30f;
        int s = 0;
        if (p < end) {
            s = g_csr[p];
            e = lrelu(g_as[s] + add);
        }
        float cm = e;
#pragma unroll
        for (int o = 16; o; o >>= 1) cm = fmaxf(cm, __shfl_xor_sync(0xffffffffu, cm, o));
        if (cm > m) {
            float sc = __expf(m - cm);
            ax *= sc; ay *= sc; az *= sc; aw *= sc; dsum *= sc;
            m = cm;
        }
        float wj = (p < end) ? __expf(e - m) : 0.f;
        dsum += wj;
        sw_buf[wslot][lane] = wj;
        ss_buf[wslot][lane] = s;
        __syncwarp();
        int cnt = min(32, end - pb);
#pragma unroll 8
        for (int k = 0; k < cnt; k++) {
            float wk = sw_buf[wslot][k];
            int sk = ss_buf[wslot][k];
            uint2 gu = ((const uint2*)(Hh + (size_t)sk * CC))[lane];
            float2 glo = __half22float2(*reinterpret_cast<__half2*>(&gu.x));
            float2 ghi = __half22float2(*reinterpret_cast<__half2*>(&gu.y));
            ax += glo.x * wk;
            ay += glo.y * wk;
            az += ghi.x * wk;
            aw += ghi.y * wk;
        }
        __syncwarp();
    }
#pragma unroll
    for (int o = 16; o; o >>= 1) dsum += __shfl_xor_sync(0xffffffffu, dsum, o);
    float inv = 1.0f / dsum;

    float4 bv = ((const float4*)bias)[lane];
    float4 r;
    r.x = fmaxf(ax * inv + bv.x, 0.f);
    r.y = fmaxf(ay * inv + bv.y, 0.f);
    r.z = fmaxf(az * inv + bv.z, 0.f);
    r.w = fmaxf(aw * inv + bv.w, 0.f);
    return r;
}

// layer 1: write fp16 output (identical values to what GEMM-2 would convert)
__global__ void k_agg1(const __half* __restrict__ Hh, __half* __restrict__ OUT,
                       const float* __restrict__ bias) {
    __shared__ float s_w[8][32];
    __shared__ int   s_s[8][32];
    int gw = (blockIdx.x * blockDim.x + threadIdx.x) >> 5;
    if (gw >= NN) return;
    int lane = threadIdx.x & 31, ws = threadIdx.x >> 5;
    float4 r = agg_node(Hh, bias, gw, lane, ws, s_w, s_s);
    __half2 o0 = __floats2half2_rn(r.x, r.y);
    __half2 o1 = __floats2half2_rn(r.z, r.w);
    ((uint2*)(OUT + (size_t)gw * CC))[lane] =
        make_uint2(*reinterpret_cast<uint32_t*>(&o0), *reinterpret_cast<uint32_t*>(&o1));
}

__global__ void k_agg2_heads(const __half* __restrict__ Hh,
                             const float* __restrict__ bias,
                             const float* __restrict__ Wf, const float* __restrict__ bf,
                             const float* __restrict__ Ws, const float* __restrict__ bs,
                             float* __restrict__ out) {
    __shared__ float s_w[8][32];
    __shared__ int   s_s[8][32];
    int gw = (blockIdx.x * blockDim.x + threadIdx.x) >> 5;
    if (gw >= NN) return;
    int lane = threadIdx.x & 31, ws = threadIdx.x >> 5;
    float4 r = agg_node(Hh, bias, gw, lane, ws, s_w, s_s);

#pragma unroll
    for (int q = 0; q < 3; q++) {
        float4 w = ((const float4*)(Wf + q * CC))[lane];
        float p = r.x * w.x + r.y * w.y + r.z * w.z + r.w * w.w;
#pragma unroll
        for (int o = 16; o; o >>= 1) p += __shfl_xor_sync(0xffffffffu, p, o);
        if (lane == 0) out[(size_t)gw * 3 + q] = p + bf[q];
    }
#pragma unroll
    for (int q = 0; q < 7; q++) {
        float4 w = ((const float4*)(Ws + q * CC))[lane];
        float p = r.x * w.x + r.y * w.y + r.z * w.z + r.w * w.w;
#pragma unroll
        for (int o = 16; o; o >>= 1) p += __shfl_xor_sync(0xffffffffu, p, o);
        if (lane == 0) out[(size_t)NN * 3 + (size_t)gw * 7 + q] = p + bs[q];
    }
}

// ---------------- launch ----------------------------------------------------
extern "C" void kernel_launch(void* const* d_in, const int* in_sizes, int n_in,
                              void* d_out, int out_size) {
    const float* x      = (const float*)d_in[0];
    const void*  ei     = d_in[1];
    const float* W1     = (const float*)d_in[2];
    const float* a_src1 = (const float*)d_in[3];
    const float* a_dst1 = (const float*)d_in[4];
    const float* b1     = (const float*)d_in[5];
    const float* W2     = (const float*)d_in[6];
    const float* a_src2 = (const float*)d_in[7];
    const float* a_dst2 = (const float*)d_in[8];
    const float* b2     = (const float*)d_in[9];
    const float* Wf     = (const float*)d_in[10];
    const float* bf     = (const float*)d_in[11];
    const float* Ws     = (const float*)d_in[12];
    const float* bs     = (const float*)d_in[13];
    float* out = (float*)d_out;

    cudaFuncSetAttribute(k_gemm_mma, cudaFuncAttributeMaxDynamicSharedMemorySize, SMEM_GEMM);

    __half *gH, *gBh, *gXh, *gW1h, *gW2h;
    cudaGetSymbolAddress((void**)&gH,   g_H);
    cudaGetSymbolAddress((void**)&gBh,  g_Bh);
    cudaGetSymbolAddress((void**)&gXh,  g_Xh);
    cudaGetSymbolAddress((void**)&gW1h, g_W1h);
    cudaGetSymbolAddress((void**)&gW2h, g_W2h);

    int gemm_grid = (NN + 63) / 64;      // 1563
    int agg_grid  = (NN + 7) / 8;        // 12500
    int conv_grid = (NN * CC / 4 + 255) / 256;  // 12500

    // launch order keeps gemm1 at index 3 (= ncu capture slot 5)
    k_detect<<<1, 256>>>(ei);
    k_tohalf<<<conv_grid, 256>>>(x, W1, W2);   // also zeroes g_cur
    k_convert<<<EE / 256, 256>>>(ei);
    k_gemm_mma<<<gemm_grid, 128, SMEM_GEMM>>>(gXh, gW1h, a_src1, a_dst1, gH);
    k_scan1<<<NB_SCAN, SCAN_B>>>();
    k_scan2<<<1, 128>>>();
    k_scan3<<<(NN + 255) / 256, 256>>>();
    k_scatter<<<EE / 256, 256>>>();

    // layer 1 aggregate (fp16 out)
    k_agg1<<<agg_grid, 256>>>(gH, gBh, b1);

    // layer 2 GEMM + fused aggregate/heads
    k_gemm_mma<<<gemm_grid, 128, SMEM_GEMM>>>(gBh, gW2h, a_src2, a_dst2, gH);
    k_agg2_heads<<<agg_grid, 256>>>(gH, b2, Wf, bf, Ws, bs, out);

    (void)in_sizes; (void)n_in; (void)out_size;
}

// round 15
// speedup vs baseline: 1.1184x; 1.0168x over previous
#include <cuda_runtime.h>
#include <cuda_fp16.h>
#include <cstdint>

#define NN 100000
#define EE 1600000
#define CC 128
#define SCAN_B 1024
#define NB_SCAN ((NN + SCAN_B - 1) / SCAN_B)   // 98

typedef unsigned long long ull;

// ---------------- scratch (static device globals) ---------------------------
__device__ __half g_H[(size_t)NN * CC];   // gemm output (value matrix), fp16
__device__ __half g_Bh[(size_t)NN * CC];  // layer-1 aggregate output, fp16
__device__ __half g_Xh[(size_t)NN * CC];  // fp16 copy of input x
__device__ __half g_W1h[CC * CC];
__device__ __half g_W2h[CC * CC];
__device__ float  g_as[NN];
__device__ float  g_ad[NN];
__device__ int    g_src[EE];
__device__ int    g_dst[EE];
__device__ int    g_csr[EE];
__device__ int    g_off[NN + 1];
__device__ int    g_cur[NN];
__device__ int    g_bsum[NB_SCAN];
__device__ int    g_is64;

__device__ __forceinline__ float lrelu(float x) { return x > 0.f ? x : 0.2f * x; }

__device__ __forceinline__ uint32_t smem_u32(const void* p) {
    uint32_t a;
    asm("{ .reg .u64 t; cvta.to.shared.u64 t, %1; cvt.u32.u64 %0, t; }" : "=r"(a) : "l"(p));
    return a;
}

__device__ __forceinline__ void cp16(uint32_t dst, const void* src, int sz) {
    asm volatile("cp.async.cg.shared.global [%0], [%1], 16, %2;"
                 :: "r"(dst), "l"(src), "r"(sz) : "memory");
}
#define CP_COMMIT() asm volatile("cp.async.commit_group;" ::: "memory")
#define CP_WAIT0()  asm volatile("cp.async.wait_group 0;" ::: "memory")

#define LDSM4(r0, r1, r2, r3, addr) \
    asm volatile("ldmatrix.sync.aligned.m8n8.x4.shared.b16 {%0,%1,%2,%3}, [%4];" \
                 : "=r"(r0), "=r"(r1), "=r"(r2), "=r"(r3) : "r"(addr))

#define MMA16816(c, a, b0v, b1v) \
    asm volatile("mma.sync.aligned.m16n8k16.row.col.f32.f16.f16.f32 " \
                 "{%0,%1,%2,%3}, {%4,%5,%6,%7}, {%8,%9}, {%0,%1,%2,%3};" \
                 : "+f"((c)[0]), "+f"((c)[1]), "+f"((c)[2]), "+f"((c)[3]) \
                 : "r"((a)[0]), "r"((a)[1]), "r"((a)[2]), "r"((a)[3]), \
                   "r"(b0v), "r"(b1v))

// ---------------- fp16 pre-conversion + g_cur zero + dtype detect -----------
__global__ void k_tohalf(const float* __restrict__ x,
                         const float* __restrict__ W1, const float* __restrict__ W2,
                         const void* ei) {
    int i = blockIdx.x * blockDim.x + threadIdx.x;
    if (blockIdx.x == 0) {
        // edge-index dtype probe (block 0 only)
        const unsigned long long* p = (const unsigned long long*)ei;
        int b = 0;
        for (int k = threadIdx.x; k < 1024; k += blockDim.x)
            if ((p[k] >> 32) != 0ull) b = 1;
        int any = __syncthreads_or(b);
        if (threadIdx.x == 0) g_is64 = any ? 0 : 1;
    }
    if (i < NN) g_cur[i] = 0;
    const float4* x4 = (const float4*)x;
    uint2* xo = (uint2*)g_Xh;
    if (i < NN * CC / 4) {
        float4 v = x4[i];
        __half2 a = __floats2half2_rn(v.x, v.y);
        __half2 b = __floats2half2_rn(v.z, v.w);
        xo[i] = make_uint2(*reinterpret_cast<uint32_t*>(&a), *reinterpret_cast<uint32_t*>(&b));
    }
    if (i < CC * CC / 4) {
        float4 v = ((const float4*)W1)[i];
        __half2 a = __floats2half2_rn(v.x, v.y);
        __half2 b = __floats2half2_rn(v.z, v.w);
        ((uint2*)g_W1h)[i] = make_uint2(*reinterpret_cast<uint32_t*>(&a), *reinterpret_cast<uint32_t*>(&b));
        float4 w = ((const float4*)W2)[i];
        __half2 c = __floats2half2_rn(w.x, w.y);
        __half2 d = __floats2half2_rn(w.z, w.w);
        ((uint2*)g_W2h)[i] = make_uint2(*reinterpret_cast<uint32_t*>(&c), *reinterpret_cast<uint32_t*>(&d));
    }
}

__global__ void k_convert(const void* ei) {
    int j = blockIdx.x * blockDim.x + threadIdx.x;
    if (j >= EE) return;
    int s, d;
    if (g_is64) {
        const long long* p = (const long long*)ei;
        s = (int)p[j];
        d = (int)p[EE + j];
    } else {
        const int* p = (const int*)ei;
        s = p[j];
        d = p[EE + j];
    }
    g_src[j] = s;
    g_dst[j] = d;
    atomicAdd(&g_cur[d], 1);
}

// ---------------- scan: block-local exclusive + inline cross-block sum ------
__global__ void k_scan1() {
    __shared__ int sh[SCAN_B];
    int tid = threadIdx.x;
    int i = blockIdx.x * SCAN_B + tid;
    int v = (i < NN) ? g_cur[i] : 0;
    sh[tid] = v;
    __syncthreads();
    for (int off = 1; off < SCAN_B; off <<= 1) {
        int t = (tid >= off) ? sh[tid - off] : 0;
        __syncthreads();
        sh[tid] += t;
        __syncthreads();
    }
    if (i < NN) g_off[i] = sh[tid] - v;           // exclusive within block
    if (tid == SCAN_B - 1) g_bsum[blockIdx.x] = sh[tid];   // block total
}

// scan3: each 256-thread block covers one quarter of a scan1 block; its base
// offset = sum of g_bsum[0 .. B-1], B = blockIdx>>2, reduced in-block.
__global__ void k_scan3() {
    __shared__ int red[256];
    int t = threadIdx.x;
    int B = blockIdx.x >> 2;                      // 1024/256
    int v = (t < B) ? g_bsum[t] : 0;              // B <= 97 < 256
    red[t] = v;
    __syncthreads();
#pragma unroll
    for (int o = 128; o; o >>= 1) {
        if (t < o) red[t] += red[t + o];
        __syncthreads();
    }
    int base = red[0];
    int i = blockIdx.x * 256 + t;
    if (i < NN) {
        int val = g_off[i] + base;
        g_off[i] = val;
        g_cur[i] = val;
    }
    if (i == 0) g_off[NN] = EE;
}

__global__ void k_scatter() {
    int j = blockIdx.x * blockDim.x + threadIdx.x;
    if (j >= EE) return;
    int d = g_dst[j];
    int p = atomicAdd(&g_cur[d], 1);
    g_csr[p] = g_src[j];
}

// ---------------- HMMA GEMM: H = Xh @ Wh^T + attention logits ---------------
// M=64 tile, 128 threads (4 warps, each 32x64), 4 CTAs/SM for phase overlap.
#define ROWB 256                 // bytes per smem row (128 halves)
#define DPITCH 136               // halves per row of D staging (272B, 16B-aligned)
#define SMA 16384                // A tile: 64 rows x 256B
#define SMB 32768                // B tile: 128 rows x 256B
#define SMEM_GEMM (SMA + SMB + 1024)

__global__ void __launch_bounds__(128, 4)
k_gemm_mma(const __half* __restrict__ Xh, const __half* __restrict__ Wh,
           const float* __restrict__ avs, const float* __restrict__ avd,
           __half* __restrict__ H) {
    extern __shared__ char sm[];
    char* smA = sm;
    char* smB = sm + SMA;
    float* sAV = (float*)(sm + SMA + SMB);   // [0:128) avs, [128:256) avd
    int tid = threadIdx.x;
    int lane = tid & 31, wid = tid >> 5;
    int row0 = blockIdx.x * 64;

    uint32_t aBase = smem_u32(smA), bBase = smem_u32(smB);

    // ---- async load: X tile (64 rows, zfill tail) + W (128 rows) -----------
#pragma unroll
    for (int i = tid; i < 1024; i += 128) {
        int r = i >> 4, c8 = i & 15;
        int gr = row0 + r;
        int sz = (gr < NN) ? 16 : 0;
        const __half* src = Xh + (size_t)(gr < NN ? gr : 0) * CC + c8 * 8;
        cp16(aBase + r * ROWB + (((c8 ^ (r & 7)) & 15) << 4), src, sz);
    }
#pragma unroll
    for (int i = tid; i < 2048; i += 128) {
        int r = i >> 4, c8 = i & 15;
        cp16(bBase + r * ROWB + (((c8 ^ (r & 7)) & 15) << 4), Wh + r * CC + c8 * 8, 16);
    }
    CP_COMMIT();
    // stage attention vectors while cp.async is in flight
    sAV[tid] = avs[tid & 127];
    if (tid < 128) sAV[128 + tid] = avd[tid];
    CP_WAIT0();
    __syncthreads();

    // ---- mainloop: warpM = wid&1 (32 rows), warpN = wid>>1 (64 cols) -------
    int warpM = wid & 1, warpN = wid >> 1;
    float acc[2][8][4];
#pragma unroll
    for (int mt = 0; mt < 2; mt++)
#pragma unroll
        for (int nt = 0; nt < 8; nt++)
#pragma unroll
            for (int j = 0; j < 4; j++) acc[mt][nt][j] = 0.f;

#pragma unroll
    for (int ks = 0; ks < 8; ks++) {
        uint32_t kh = (uint32_t)(ks * 2 + (lane >> 4));
        uint32_t ar[2][4];
#pragma unroll
        for (int mt = 0; mt < 2; mt++) {
            int r = warpM * 32 + mt * 16 + (lane & 15);
            uint32_t addr = aBase + r * ROWB + (((kh ^ (uint32_t)(r & 7)) & 15u) << 4);
            LDSM4(ar[mt][0], ar[mt][1], ar[mt][2], ar[mt][3], addr);
        }
        uint32_t br[4][4];
#pragma unroll
        for (int nt = 0; nt < 4; nt++) {
            int n = warpN * 64 + nt * 16 + (lane & 15);
            uint32_t addr = bBase + n * ROWB + (((kh ^ (uint32_t)(n & 7)) & 15u) << 4);
            LDSM4(br[nt][0], br[nt][1], br[nt][2], br[nt][3], addr);
        }
#pragma unroll
        for (int mt = 0; mt < 2; mt++)
#pragma unroll
            for (int nt = 0; nt < 4; nt++) {
                MMA16816(acc[mt][nt * 2 + 0], ar[mt], br[nt][0], br[nt][2]);
                MMA16816(acc[mt][nt * 2 + 1], ar[mt], br[nt][1], br[nt][3]);
            }
    }

    // ---- stage D into smem (reuse A/B regions), pitch 136 halves -----------
    __syncthreads();
    __half* D = (__half*)sm;
    int q = lane & 3, g = lane >> 2;
#pragma unroll
    for (int mt = 0; mt < 2; mt++) {
        int r0 = warpM * 32 + mt * 16 + g;
        int r1 = r0 + 8;
#pragma unroll
        for (int n8 = 0; n8 < 8; n8++) {
            int col = warpN * 64 + n8 * 8 + 2 * q;
            __half2 lo = __floats2half2_rn(acc[mt][n8][0], acc[mt][n8][1]);
            __half2 hi = __floats2half2_rn(acc[mt][n8][2], acc[mt][n8][3]);
            *(__half2*)(D + r0 * DPITCH + col) = lo;
            *(__half2*)(D + r1 * DPITCH + col) = hi;
        }
    }
    __syncthreads();

    // ---- coalesced H store + logits (2 threads per row, 64 rows) -----------
    {
        int r = tid >> 1, hhalf = tid & 1;
        int gr = row0 + r;
        const __half* drow = D + r * DPITCH + hhalf * 64;
        const float4* av4 = (const float4*)(sAV + hhalf * 64);
        const float4* ad4 = (const float4*)(sAV + 128 + hhalf * 64);
        float ps = 0.f, pd = 0.f;
        uint4 chunks[8];
#pragma unroll
        for (int i = 0; i < 8; i++) chunks[i] = *(const uint4*)(drow + i * 8);
#pragma unroll
        for (int i = 0; i < 8; i++) {
            const uint32_t* cw = (const uint32_t*)&chunks[i];
            float4 va = av4[i * 2], vb = av4[i * 2 + 1];
            float4 wa = ad4[i * 2], wb = ad4[i * 2 + 1];
            float2 f0 = __half22float2(*reinterpret_cast<const __half2*>(&cw[0]));
            float2 f1 = __half22float2(*reinterpret_cast<const __half2*>(&cw[1]));
            float2 f2 = __half22float2(*reinterpret_cast<const __half2*>(&cw[2]));
            float2 f3 = __half22float2(*reinterpret_cast<const __half2*>(&cw[3]));
            ps += f0.x * va.x + f0.y * va.y + f1.x * va.z + f1.y * va.w
                + f2.x * vb.x + f2.y * vb.y + f3.x * vb.z + f3.y * vb.w;
            pd += f0.x * wa.x + f0.y * wa.y + f1.x * wa.z + f1.y * wa.w
                + f2.x * wb.x + f2.y * wb.y + f3.x * wb.z + f3.y * wb.w;
        }
        float pso = ps + __shfl_xor_sync(0xffffffffu, ps, 1);
        float pdo = pd + __shfl_xor_sync(0xffffffffu, pd, 1);
        if (gr < NN) {
            uint4* dst = (uint4*)(H + (size_t)gr * CC + hhalf * 64);
#pragma unroll
            for (int i = 0; i < 8; i++) dst[i] = chunks[i];
            if (hhalf == 0) {
                g_as[gr] = pso;
                g_ad[gr] = pdo;
            }
        }
    }
}

// ---------------- aggregate core: online softmax, warp per dst --------------
__device__ __forceinline__ float4 agg_node(const __half* __restrict__ Hh,
                                           const float* __restrict__ bias,
                                           int d, int lane, int wslot,
                                           float sw_buf[8][32], int ss_buf[8][32]) {
    int beg = g_off[d], end = g_off[d + 1];
    float add = g_ad[d];
    float m = lrelu(g_as[d] + add);     // self-loop logit

    uint2 hu = ((const uint2*)(Hh + (size_t)d * CC))[lane];
    float2 lo = __half22float2(*reinterpret_cast<__half2*>(&hu.x));
    float2 hi = __half22float2(*reinterpret_cast<__half2*>(&hu.y));
    float ax = lo.x, ay = lo.y, az = hi.x, aw = hi.y;
    float dsum = (lane == 0) ? 1.f : 0.f;

    for (int pb = beg; pb < end; pb += 32) {
        int p = pb + lane;
        float e = -1e30f;
        int s = 0;
        if (p < end) {
            s = g_csr[p];
            e = lrelu(g_as[s] + add);
        }
        float cm = e;
#pragma unroll
        for (int o = 16; o; o >>= 1) cm = fmaxf(cm, __shfl_xor_sync(0xffffffffu, cm, o));
        if (cm > m) {
            float sc = __expf(m - cm);
            ax *= sc; ay *= sc; az *= sc; aw *= sc; dsum *= sc;
            m = cm;
        }
        float wj = (p < end) ? __expf(e - m) : 0.f;
        dsum += wj;
        sw_buf[wslot][lane] = wj;
        ss_buf[wslot][lane] = s;
        __syncwarp();
        int cnt = min(32, end - pb);
#pragma unroll 8
        for (int k = 0; k < cnt; k++) {
            float wk = sw_buf[wslot][k];
            int sk = ss_buf[wslot][k];
            uint2 gu = ((const uint2*)(Hh + (size_t)sk * CC))[lane];
            float2 glo = __half22float2(*reinterpret_cast<__half2*>(&gu.x));
            float2 ghi = __half22float2(*reinterpret_cast<__half2*>(&gu.y));
            ax += glo.x * wk;
            ay += glo.y * wk;
            az += ghi.x * wk;
            aw += ghi.y * wk;
        }
        __syncwarp();
    }
#pragma unroll
    for (int o = 16; o; o >>= 1) dsum += __shfl_xor_sync(0xffffffffu, dsum, o);
    float inv = 1.0f / dsum;

    float4 bv = ((const float4*)bias)[lane];
    float4 r;
    r.x = fmaxf(ax * inv + bv.x, 0.f);
    r.y = fmaxf(ay * inv + bv.y, 0.f);
    r.z = fmaxf(az * inv + bv.z, 0.f);
    r.w = fmaxf(aw * inv + bv.w, 0.f);
    return r;
}

// layer 1: write fp16 output (identical values to what GEMM-2 would convert)
__global__ void k_agg1(const __half* __restrict__ Hh, __half* __restrict__ OUT,
                       const float* __restrict__ bias) {
    __shared__ float s_w[8][32];
    __shared__ int   s_s[8][32];
    int gw = (blockIdx.x * blockDim.x + threadIdx.x) >> 5;
    if (gw >= NN) return;
    int lane = threadIdx.x & 31, ws = threadIdx.x >> 5;
    float4 r = agg_node(Hh, bias, gw, lane, ws, s_w, s_s);
    __half2 o0 = __floats2half2_rn(r.x, r.y);
    __half2 o1 = __floats2half2_rn(r.z, r.w);
    ((uint2*)(OUT + (size_t)gw * CC))[lane] =
        make_uint2(*reinterpret_cast<uint32_t*>(&o0), *reinterpret_cast<uint32_t*>(&o1));
}

__global__ void k_agg2_heads(const __half* __restrict__ Hh,
                             const float* __restrict__ bias,
                             const float* __restrict__ Wf, const float* __restrict__ bf,
                             const float* __restrict__ Ws, const float* __restrict__ bs,
                             float* __restrict__ out) {
    __shared__ float s_w[8][32];
    __shared__ int   s_s[8][32];
    int gw = (blockIdx.x * blockDim.x + threadIdx.x) >> 5;
    if (gw >= NN) return;
    int lane = threadIdx.x & 31, ws = threadIdx.x >> 5;
    float4 r = agg_node(Hh, bias, gw, lane, ws, s_w, s_s);

#pragma unroll
    for (int q = 0; q < 3; q++) {
        float4 w = ((const float4*)(Wf + q * CC))[lane];
        float p = r.x * w.x + r.y * w.y + r.z * w.z + r.w * w.w;
#pragma unroll
        for (int o = 16; o; o >>= 1) p += __shfl_xor_sync(0xffffffffu, p, o);
        if (lane == 0) out[(size_t)gw * 3 + q] = p + bf[q];
    }
#pragma unroll
    for (int q = 0; q < 7; q++) {
        float4 w = ((const float4*)(Ws + q * CC))[lane];
        float p = r.x * w.x + r.y * w.y + r.z * w.z + r.w * w.w;
#pragma unroll
        for (int o = 16; o; o >>= 1) p += __shfl_xor_sync(0xffffffffu, p, o);
        if (lane == 0) out[(size_t)NN * 3 + (size_t)gw * 7 + q] = p + bs[q];
    }
}

// ---------------- launch (flat, single stream — graph-capture safe) ---------
extern "C" void kernel_launch(void* const* d_in, const int* in_sizes, int n_in,
                              void* d_out, int out_size) {
    const float* x      = (const float*)d_in[0];
    const void*  ei     = d_in[1];
    const float* W1     = (const float*)d_in[2];
    const float* a_src1 = (const float*)d_in[3];
    const float* a_dst1 = (const float*)d_in[4];
    const float* b1     = (const float*)d_in[5];
    const float* W2     = (const float*)d_in[6];
    const float* a_src2 = (const float*)d_in[7];
    const float* a_dst2 = (const float*)d_in[8];
    const float* b2     = (const float*)d_in[9];
    const float* Wf     = (const float*)d_in[10];
    const float* bf     = (const float*)d_in[11];
    const float* Ws     = (const float*)d_in[12];
    const float* bs     = (const float*)d_in[13];
    float* out = (float*)d_out;

    cudaFuncSetAttribute(k_gemm_mma, cudaFuncAttributeMaxDynamicSharedMemorySize, SMEM_GEMM);

    __half *gH, *gBh, *gXh, *gW1h, *gW2h;
    cudaGetSymbolAddress((void**)&gH,   g_H);
    cudaGetSymbolAddress((void**)&gBh,  g_Bh);
    cudaGetSymbolAddress((void**)&gXh,  g_Xh);
    cudaGetSymbolAddress((void**)&gW1h, g_W1h);
    cudaGetSymbolAddress((void**)&gW2h, g_W2h);

    int gemm_grid = (NN + 63) / 64;      // 1563
    int agg_grid  = (NN + 7) / 8;        // 12500
    int conv_grid = (NN * CC / 4 + 255) / 256;  // 12500

    // flat serial sequence (9 launches)
    k_tohalf<<<conv_grid, 256>>>(x, W1, W2, ei);      // fp16 conv + dtype probe + zero
    k_convert<<<EE / 256, 256>>>(ei);                 // decode edges + degree histogram
    k_gemm_mma<<<gemm_grid, 128, SMEM_GEMM>>>(gXh, gW1h, a_src1, a_dst1, gH);
    k_scan1<<<NB_SCAN, SCAN_B>>>();
    k_scan3<<<(NN + 255) / 256, 256>>>();
    k_scatter<<<EE / 256, 256>>>();

    // layer 1 aggregate (fp16 out)
    k_agg1<<<agg_grid, 256>>>(gH, gBh, b1);

    // layer 2 GEMM + fused aggregate/heads
    k_gemm_mma<<<gemm_grid, 128, SMEM_GEMM>>>(gBh, gW2h, a_src2, a_dst2, gH);
    k_agg2_heads<<<agg_grid, 256>>>(gH, b2, Wf, bf, Ws, bs, out);

    (void)in_sizes; (void)n_in; (void)out_size;
}